// round 15
// baseline (speedup 1.0000x reference)
#include <cuda_runtime.h>
#include <math_constants.h>
#include <cuda_fp16.h>
#include <cstdint>

// ---------------------------------------------------------------------------
// Net_40312563041045: 4-layer max-tempered MLP
//   h = 0.8 * (X @ W^T) + 0.2 * max_k(W[o,k] * x[b,k]) + b
// B=1024, 256 -> 512 -> 512 -> 512 -> 1, fp32.
//
// R15: break the gemm-warp LDS->cvt->sub->mma chain. Epilogue (and prep for
// the input) emit tf32 hi/lo splits of the activations; gemm warps stage
// XHI/XLO and do pure LDS->mma. Max warps unchanged (packed fp16 tiles).
// 64x32 tile, 256 threads (4 max + 4 gemm warps), grid 256, 2 blocks/SM.
// ---------------------------------------------------------------------------

#define BETA 0.2f

// buffer layout (float offsets)
#define XHI_F  0
#define XLO_F  2304
#define WHI_F  4608
#define WLO_F  5760
#define X16_F  6912     // 64 rows * 40 halves = 1280 float-units
#define W16_F  8192     // 32 rows * 40 halves = 640 float-units
#define BUF_F  8832
#define SMEM_BYTES (2 * BUF_F * 4)   // 70656

// ---------------- global scratch ------------------------------------------
__device__ float  g_actA[1024 * 512], g_actB[1024 * 512];
__device__ float  g_HiA[1024 * 512], g_LoA[1024 * 512];
__device__ float  g_HiB[1024 * 512], g_LoB[1024 * 512];
__device__ __half g_a16A[1024 * 512], g_a16B[1024 * 512];
__device__ float  g_Xhi[1024 * 256], g_Xlo[1024 * 256];
__device__ __half g_x16[1024 * 256];
__device__ __half g_W116[512 * 256], g_W216[512 * 512], g_W316[512 * 512];
__device__ float  g_W1hi[512 * 256], g_W1lo[512 * 256];
__device__ float  g_W2hi[512 * 512], g_W2lo[512 * 512];
__device__ float  g_W3hi[512 * 512], g_W3lo[512 * 512];

// ---------------- helpers --------------------------------------------------
__device__ __forceinline__ unsigned smem_u32(const void* p) {
    return (unsigned)__cvta_generic_to_shared(p);
}
__device__ __forceinline__ void cp16(unsigned dst, const void* src) {
    asm volatile("cp.async.ca.shared.global [%0], [%1], 16;\n" :: "r"(dst), "l"(src));
}
__device__ __forceinline__ float tf32_of(float v) {
    uint32_t t;
    asm("cvt.rna.tf32.f32 %0, %1;" : "=r"(t) : "f"(v));
    return __uint_as_float(t);
}
__device__ __forceinline__ void mma_tf32(float c[4], const uint32_t a[4],
                                         const uint32_t b[2]) {
    asm volatile(
        "mma.sync.aligned.m16n8k8.row.col.f32.tf32.tf32.f32 "
        "{%0,%1,%2,%3}, {%4,%5,%6,%7}, {%8,%9}, {%0,%1,%2,%3};"
        : "+f"(c[0]), "+f"(c[1]), "+f"(c[2]), "+f"(c[3])
        : "r"(a[0]), "r"(a[1]), "r"(a[2]), "r"(a[3]), "r"(b[0]), "r"(b[1]));
}

// ---------------- prep ------------------------------------------------------
// x -> {hi, lo, fp16}; W1/2/3 -> {hi, lo, fp16}
// float4 ranges: x [0,65536) W1 [65536,98304) W2 [98304,163840) W3 [163840,229376)
__global__ void __launch_bounds__(256)
prep_kernel(const float* __restrict__ x, const float* __restrict__ W1,
            const float* __restrict__ W2, const float* __restrict__ W3)
{
    const int i = blockIdx.x * 256 + threadIdx.x;
    const float* src; float* hi; float* lo; __half* h16; int off;
    if (i < 65536)       { src = x;  hi = g_Xhi;  lo = g_Xlo;  h16 = g_x16;  off = i; }
    else if (i < 98304)  { src = W1; hi = g_W1hi; lo = g_W1lo; h16 = g_W116; off = i - 65536; }
    else if (i < 163840) { src = W2; hi = g_W2hi; lo = g_W2lo; h16 = g_W216; off = i - 98304; }
    else                 { src = W3; hi = g_W3hi; lo = g_W3lo; h16 = g_W316; off = i - 163840; }
    float4 v = ((const float4*)src)[off];
    float4 h, l;
    h.x = tf32_of(v.x); l.x = v.x - h.x;
    h.y = tf32_of(v.y); l.y = v.y - h.y;
    h.z = tf32_of(v.z); l.z = v.z - h.z;
    h.w = tf32_of(v.w); l.w = v.w - h.w;
    ((float4*)hi)[off] = h;
    ((float4*)lo)[off] = l;
    ((__half2*)h16)[off * 2]     = __floats2half2_rn(v.x, v.y);
    ((__half2*)h16)[off * 2 + 1] = __floats2half2_rn(v.z, v.w);
}

// ---------------- fused warp-specialized layer ------------------------------
// Grid 256 = 16 (m: 64 rows) x 16 (n: 32 cols), 256 threads:
//   warps 0-3: MAX term, packed fp16 over staged fp16 tiles
//   warps 4-7: LINEAR term, mma.sync tf32 3-pass, pure LDS->mma
template <int K>
__global__ void __launch_bounds__(256, 2)
layer_fused(const float* __restrict__ Xhi, const float* __restrict__ Xlo,
            const __half* __restrict__ X16g,
            const float* __restrict__ Whi, const float* __restrict__ Wlo,
            const __half* __restrict__ W16g, const float* __restrict__ bias,
            float* __restrict__ act, float* __restrict__ Ahi,
            float* __restrict__ Alo, __half* __restrict__ act16, int O)
{
    extern __shared__ float smf[];
    const unsigned sb = smem_u32(smf);
    const int tid = threadIdx.x;
    const int wid = tid >> 5;
    const int lane = tid & 31;
    const int m0 = (blockIdx.x & 15) * 64;
    const int n0 = (blockIdx.x >> 4) * 32;

    // staging maps
    const int xrow = tid >> 2;          // 0..63
    const int xq   = (tid & 3) * 4;     // XHI/XLO: 2 chunks each (xq, xq+16)
    const int xhc  = (tid & 3) * 8;     // X16: 1 chunk
    const int wrow = tid >> 3;          // 0..31 (WHI/WLO: 1 chunk each)
    const int wq   = (tid & 7) * 4;
    const int w16r = (tid & 127) >> 2;  // 0..31 (W16: threads 0-127)
    const int w16c = (tid & 3) * 8;

    const float*  xhg = Xhi  + (size_t)(m0 + xrow) * K + xq;
    const float*  xlg = Xlo  + (size_t)(m0 + xrow) * K + xq;
    const __half* x6g = X16g + (size_t)(m0 + xrow) * K + xhc;
    const float*  whg = Whi  + (size_t)(n0 + wrow) * K + wq;
    const float*  wlg = Wlo  + (size_t)(n0 + wrow) * K + wq;
    const __half* w6g = W16g + (size_t)(n0 + w16r) * K + w16c;

    // max-role mapping (threads 0-127)
    const int tcol = tid & 7;
    const int trow = tid >> 3;
    // gemm-role mapping (verified fragment indices)
    const int gw = wid - 4;
    const int wm = gw & 1;
    const int wn = gw >> 1;
    const int lr = lane >> 2;
    const int lw = lane & 3;

    __half2 mx[4][4];
    const __half2 ninf = __halves2half2(__ushort_as_half(0xFC00),
                                        __ushort_as_half(0xFC00));
#pragma unroll
    for (int i = 0; i < 4; i++)
#pragma unroll
        for (int j = 0; j < 4; j++) mx[i][j] = ninf;
    float acc[2][2][4];
#pragma unroll
    for (int mt = 0; mt < 2; mt++)
#pragma unroll
        for (int nt = 0; nt < 2; nt++)
#pragma unroll
            for (int e = 0; e < 4; e++) acc[mt][nt][e] = 0.0f;

    const int NCH = K / 32;

    auto stage = [&](int k0, unsigned bbF) {
        const unsigned bbB = bbF * 4u;
        const unsigned xo = (unsigned)(xrow * 36 + xq) * 4;
        cp16(sb + bbB + xo,                         xhg + k0);
        cp16(sb + bbB + xo + 64,                    xhg + k0 + 16);
        cp16(sb + bbB + XLO_F * 4u + xo,            xlg + k0);
        cp16(sb + bbB + XLO_F * 4u + xo + 64,       xlg + k0 + 16);
        cp16(sb + bbB + (WHI_F + wrow * 36 + wq) * 4u, whg + k0);
        cp16(sb + bbB + (WLO_F + wrow * 36 + wq) * 4u, wlg + k0);
        cp16(sb + bbB + X16_F * 4u + (unsigned)(xrow * 40 + xhc) * 2, x6g + k0);
        if (tid < 128)
            cp16(sb + bbB + W16_F * 4u + (unsigned)(w16r * 40 + w16c) * 2, w6g + k0);
        asm volatile("cp.async.commit_group;\n");
    };

    stage(0, 0);

    for (int c = 0; c < NCH; ++c) {
        const int buf = c & 1;
        if (c + 1 < NCH) {
            stage((c + 1) * 32, (unsigned)((buf ^ 1) * BUF_F));
            asm volatile("cp.async.wait_group 1;\n");
        } else {
            asm volatile("cp.async.wait_group 0;\n");
        }
        __syncthreads();

        const float* B = smf + buf * BUF_F;

        if (wid < 4) {
            // -------- MAX warps: packed fp16 over staged tiles -------------
            const __half* X16 = (const __half*)(B + X16_F);
            const __half* W16 = (const __half*)(B + W16_F);
#pragma unroll
            for (int kk = 0; kk < 32; kk += 8) {
                uint4 xv[4], wv[4];
#pragma unroll
                for (int i = 0; i < 4; i++)
                    xv[i] = *(const uint4*)&X16[(trow * 4 + i) * 40 + kk];
#pragma unroll
                for (int j = 0; j < 4; j++)
                    wv[j] = *(const uint4*)&W16[(tcol + 8 * j) * 40 + kk];
#pragma unroll
                for (int i = 0; i < 4; i++)
#pragma unroll
                    for (int j = 0; j < 4; j++) {
                        const __half2* xh = (const __half2*)&xv[i];
                        const __half2* wh = (const __half2*)&wv[j];
#pragma unroll
                        for (int e = 0; e < 4; e++)
                            mx[i][j] = __hmax2(mx[i][j], __hmul2(xh[e], wh[e]));
                    }
            }
        } else {
            // -------- GEMM warps: pure LDS -> mma (everything pre-split) ---
            const uint32_t* XH = (const uint32_t*)(B + XHI_F);
            const uint32_t* XL = (const uint32_t*)(B + XLO_F);
            const uint32_t* WH = (const uint32_t*)(B + WHI_F);
            const uint32_t* WL = (const uint32_t*)(B + WLO_F);
#pragma unroll
            for (int kc = 0; kc < 32; kc += 8) {
                uint32_t ah[2][4], al[2][4];
#pragma unroll
                for (int mt = 0; mt < 2; mt++) {
                    const int base = (wm * 32 + mt * 16 + lr) * 36 + kc + lw;
                    ah[mt][0] = XH[base];     ah[mt][1] = XH[base + 8 * 36];
                    ah[mt][2] = XH[base + 4]; ah[mt][3] = XH[base + 8 * 36 + 4];
                    al[mt][0] = XL[base];     al[mt][1] = XL[base + 8 * 36];
                    al[mt][2] = XL[base + 4]; al[mt][3] = XL[base + 8 * 36 + 4];
                }
#pragma unroll
                for (int nt = 0; nt < 2; nt++) {
                    const int base = (wn * 16 + nt * 8 + lr) * 36 + kc + lw;
                    uint32_t bh[2] = { WH[base], WH[base + 4] };
                    uint32_t bl[2] = { WL[base], WL[base + 4] };
#pragma unroll
                    for (int mt = 0; mt < 2; mt++) {
                        mma_tf32(acc[mt][nt], ah[mt], bh);
                        mma_tf32(acc[mt][nt], ah[mt], bl);
                        mma_tf32(acc[mt][nt], al[mt], bh);
                    }
                }
            }
        }
        __syncthreads();
    }

    // ---- epilogue ----
    float* mxs = smf;   // [64][36]; buffer 0 free (last chunk uses buf 1)
    if (wid < 4) {
#pragma unroll
        for (int i = 0; i < 4; i++)
#pragma unroll
            for (int j = 0; j < 4; j++) {
                float m = fmaxf(__low2float(mx[i][j]), __high2float(mx[i][j]));
                mxs[(trow * 4 + i) * 36 + tcol + 8 * j] = BETA * m;
            }
    }
    __syncthreads();

    if (wid >= 4) {
#pragma unroll
        for (int mt = 0; mt < 2; mt++) {
            const int r0 = wm * 32 + mt * 16 + lr;
#pragma unroll
            for (int nt = 0; nt < 2; nt++) {
                const int cc = wn * 16 + nt * 8 + lw * 2;
                const float2 bia = *(const float2*)&bias[n0 + cc];

                float a0 = 0.8f * acc[mt][nt][0] + bia.x + mxs[r0 * 36 + cc];
                float a1 = 0.8f * acc[mt][nt][1] + bia.y + mxs[r0 * 36 + cc + 1];
                float a2 = 0.8f * acc[mt][nt][2] + bia.x + mxs[(r0 + 8) * 36 + cc];
                float a3 = 0.8f * acc[mt][nt][3] + bia.y + mxs[(r0 + 8) * 36 + cc + 1];

                const size_t o0 = (size_t)(m0 + r0) * O + n0 + cc;
                const size_t o1 = (size_t)(m0 + r0 + 8) * O + n0 + cc;
                *(float2*)&act[o0] = make_float2(a0, a1);
                *(float2*)&act[o1] = make_float2(a2, a3);
                *(__half2*)&act16[o0] = __floats2half2_rn(a0, a1);
                *(__half2*)&act16[o1] = __floats2half2_rn(a2, a3);

                float h0 = tf32_of(a0), h1 = tf32_of(a1);
                float h2 = tf32_of(a2), h3 = tf32_of(a3);
                *(float2*)&Ahi[o0] = make_float2(h0, h1);
                *(float2*)&Ahi[o1] = make_float2(h2, h3);
                *(float2*)&Alo[o0] = make_float2(a0 - h0, a1 - h1);
                *(float2*)&Alo[o1] = make_float2(a2 - h2, a3 - h3);
            }
        }
    }
}

// ---------------- final layer ----------------------------------------------
__global__ void __launch_bounds__(256)
layer4_kernel(const float* __restrict__ X, const float* __restrict__ W,
              const float* __restrict__ bias, float* __restrict__ out, int B)
{
    const int row = blockIdx.x * 8 + (threadIdx.x >> 5);
    const int lane = threadIdx.x & 31;
    if (row >= B) return;

    const float4* xr = (const float4*)(X + (size_t)row * 512);
    const float4* wr = (const float4*)W;

    float acc = 0.0f;
    float mx = -CUDART_INF_F;
#pragma unroll
    for (int it = 0; it < 4; ++it) {
        float4 x = xr[lane + 32 * it];
        float4 w = wr[lane + 32 * it];
        float p0 = x.x * w.x, p1 = x.y * w.y, p2 = x.z * w.z, p3 = x.w * w.w;
        acc += (p0 + p1) + (p2 + p3);
        mx = fmaxf(fmaxf(mx, fmaxf(p0, p1)), fmaxf(p2, p3));
    }
#pragma unroll
    for (int o = 16; o > 0; o >>= 1) {
        acc += __shfl_xor_sync(0xffffffff, acc, o);
        mx = fmaxf(mx, __shfl_xor_sync(0xffffffff, mx, o));
    }
    if (lane == 0)
        out[row] = (1.0f - BETA) * acc + BETA * mx + bias[0];
}

// ---------------- launch ----------------------------------------------------
extern "C" void kernel_launch(void* const* d_in, const int* in_sizes, int n_in,
                              void* d_out, int out_size)
{
    const float* x  = (const float*)d_in[0];
    const float* W1 = (const float*)d_in[1];
    const float* b1 = (const float*)d_in[2];
    const float* W2 = (const float*)d_in[3];
    const float* b2 = (const float*)d_in[4];
    const float* W3 = (const float*)d_in[5];
    const float* b3 = (const float*)d_in[6];
    const float* W4 = (const float*)d_in[7];
    const float* b4 = (const float*)d_in[8];
    float* out = (float*)d_out;

    const int WID = in_sizes[2];        // 512
    const int IN  = in_sizes[1] / WID;  // 256
    const int B   = in_sizes[0] / IN;   // 1024

    float *actA, *actB, *hiA, *loA, *hiB, *loB, *xhi, *xlo;
    float *w1h, *w1l, *w2h, *w2l, *w3h, *w3l;
    __half *a16A, *a16B, *x16, *w116, *w216, *w316;
    cudaGetSymbolAddress((void**)&actA, g_actA);
    cudaGetSymbolAddress((void**)&actB, g_actB);
    cudaGetSymbolAddress((void**)&hiA, g_HiA);
    cudaGetSymbolAddress((void**)&loA, g_LoA);
    cudaGetSymbolAddress((void**)&hiB, g_HiB);
    cudaGetSymbolAddress((void**)&loB, g_LoB);
    cudaGetSymbolAddress((void**)&a16A, g_a16A);
    cudaGetSymbolAddress((void**)&a16B, g_a16B);
    cudaGetSymbolAddress((void**)&xhi, g_Xhi);
    cudaGetSymbolAddress((void**)&xlo, g_Xlo);
    cudaGetSymbolAddress((void**)&x16, g_x16);
    cudaGetSymbolAddress((void**)&w116, g_W116);
    cudaGetSymbolAddress((void**)&w216, g_W216);
    cudaGetSymbolAddress((void**)&w316, g_W316);
    cudaGetSymbolAddress((void**)&w1h, g_W1hi);
    cudaGetSymbolAddress((void**)&w1l, g_W1lo);
    cudaGetSymbolAddress((void**)&w2h, g_W2hi);
    cudaGetSymbolAddress((void**)&w2l, g_W2lo);
    cudaGetSymbolAddress((void**)&w3h, g_W3hi);
    cudaGetSymbolAddress((void**)&w3l, g_W3lo);

    cudaFuncSetAttribute(layer_fused<256>,
                         cudaFuncAttributeMaxDynamicSharedMemorySize, SMEM_BYTES);
    cudaFuncSetAttribute(layer_fused<512>,
                         cudaFuncAttributeMaxDynamicSharedMemorySize, SMEM_BYTES);

    prep_kernel<<<896, 256>>>(x, W1, W2, W3);

    const dim3 blk(256);
    const dim3 grid(256);   // 16 m-tiles x 16 n-tiles of 64x32

    layer_fused<256><<<grid, blk, SMEM_BYTES>>>(xhi, xlo, x16, w1h, w1l, w116, b1,
                                                actA, hiA, loA, a16A, WID);
    layer_fused<512><<<grid, blk, SMEM_BYTES>>>(hiA, loA, a16A, w2h, w2l, w216, b2,
                                                actB, hiB, loB, a16B, WID);
    layer_fused<512><<<grid, blk, SMEM_BYTES>>>(hiB, loB, a16B, w3h, w3l, w316, b3,
                                                actA, hiA, loA, a16A, WID);
    layer4_kernel<<<B / 8, blk>>>(actA, W4, b4, out, B);
}

// round 17
// speedup vs baseline: 1.2256x; 1.2256x over previous
#include <cuda_runtime.h>
#include <math_constants.h>
#include <cuda_fp16.h>
#include <cstdint>

// ---------------------------------------------------------------------------
// Net_40312563041045: 4-layer max-tempered MLP
//   h = 0.8 * (X @ W^T) + 0.2 * max_k(W[o,k] * x[b,k]) + b
// B=1024, 256 -> 512 -> 512 -> 512 -> 1, fp32.
//
// R17 == R16 resubmitted (previous round was an infra failure, not a kernel
// result). R12 (82.0us best) + 2-PASS gemm:
//   lin = sum (xh + xl) * wh   (X split to tf32 hi+lo, W single tf32 cvt)
// Error ~2.4e-4/layer (w_lo dropped, random signs -> no sqrt(K) blowup).
// Gemm stream/chunk 176 -> ~112 issues; mma count 12 -> 8 per kc.
// Everything else byte-identical to R12: 64x32 tile, 256 threads
// (4 max warps packed-fp16 HMUL2/HMAX2 over in-kernel-converted tiles +
// 4 gemm warps), grid 256, 2 blocks/SM, no prep kernel, 4 launches.
// ---------------------------------------------------------------------------

#define BETA 0.2f
#define XTILE_F 2304    // 64 rows * 36 floats
#define BUF_F   3456    // X (64x36) + W (32x36)

__device__ float g_actA[1024 * 512];
__device__ float g_actB[1024 * 512];

__device__ __forceinline__ unsigned smem_u32(const void* p) {
    return (unsigned)__cvta_generic_to_shared(p);
}
__device__ __forceinline__ void cp16(unsigned dst, const void* src) {
    asm volatile("cp.async.ca.shared.global [%0], [%1], 16;\n" :: "r"(dst), "l"(src));
}
__device__ __forceinline__ float tf32_of(float v) {
    uint32_t t;
    asm("cvt.rna.tf32.f32 %0, %1;" : "=r"(t) : "f"(v));
    return __uint_as_float(t);
}
__device__ __forceinline__ void mma_tf32(float c[4], const uint32_t a[4],
                                         const uint32_t b[2]) {
    asm volatile(
        "mma.sync.aligned.m16n8k8.row.col.f32.tf32.tf32.f32 "
        "{%0,%1,%2,%3}, {%4,%5,%6,%7}, {%8,%9}, {%0,%1,%2,%3};"
        : "+f"(c[0]), "+f"(c[1]), "+f"(c[2]), "+f"(c[3])
        : "r"(a[0]), "r"(a[1]), "r"(a[2]), "r"(a[3]), "r"(b[0]), "r"(b[1]));
}

// ---------------- fused warp-specialized layer ------------------------------
// Grid 256 = 16 (m: 64 rows) x 16 (n: 32 cols). 256 threads:
//   warps 0-3: MAX term in packed fp16 over converted tiles
//   warps 4-7: LINEAR term, mma.sync tf32 2-pass (X hi/lo, W hi only)
template <int K>
__global__ void __launch_bounds__(256, 2)
layer_fused(const float* __restrict__ Xf, const float* __restrict__ Wf,
            const float* __restrict__ bias, float* __restrict__ act, int O)
{
    __shared__ float  smf[2][BUF_F];    // fp32 staging, double buffered
    __shared__ __half x16s[64 * 40];    // fp16 X tile (stride 40 halves)
    __shared__ __half w16s[32 * 40];    // fp16 W tile

    const unsigned sb = smem_u32(smf);
    const int tid = threadIdx.x;
    const int wid = tid >> 5;
    const int lane = tid & 31;
    const int m0 = (blockIdx.x & 15) * 64;
    const int n0 = (blockIdx.x >> 4) * 32;

    // staging: X 512 chunks (2/thread), W 256 chunks (1/thread)
    const int xrow = tid >> 2;
    const int xq   = (tid & 3) * 4;
    const int wrow = tid >> 3;
    const int wq   = (tid & 7) * 4;
    const float* xg = Xf + (size_t)(m0 + xrow) * K + xq;
    const float* wg = Wf + (size_t)(n0 + wrow) * K + wq;

    // max-role mapping (threads 0-127): rows trow*4+i, cols tcol+8*j
    const int tcol = tid & 7;
    const int trow = tid >> 3;
    // gemm-role mapping (verified R8/R11 fragment indices)
    const int gw = wid - 4;
    const int wm = gw & 1;
    const int wn = gw >> 1;
    const int lr = lane >> 2;
    const int lw = lane & 3;

    __half2 mx[4][4];
    const __half2 ninf = __halves2half2(__ushort_as_half(0xFC00),
                                        __ushort_as_half(0xFC00));
#pragma unroll
    for (int i = 0; i < 4; i++)
#pragma unroll
        for (int j = 0; j < 4; j++) mx[i][j] = ninf;
    float acc[2][2][4];
#pragma unroll
    for (int mt = 0; mt < 2; mt++)
#pragma unroll
        for (int nt = 0; nt < 2; nt++)
#pragma unroll
            for (int e = 0; e < 4; e++) acc[mt][nt][e] = 0.0f;

    const int NCH = K / 32;

    // prologue: chunk 0 -> buffer 0
    {
        const unsigned xoff = (unsigned)(xrow * 36 + xq) * 4;
        const unsigned woff = (unsigned)(XTILE_F + wrow * 36 + wq) * 4;
        cp16(sb + xoff,      xg);
        cp16(sb + xoff + 64, xg + 16);
        cp16(sb + woff,      wg);
        asm volatile("cp.async.commit_group;\n");
    }

    for (int c = 0; c < NCH; ++c) {
        const int buf = c & 1;
        if (c + 1 < NCH) {
            const int k0 = (c + 1) * 32;
            const unsigned bb = (unsigned)((buf ^ 1) * BUF_F) * 4u;
            const unsigned xoff = bb + (unsigned)(xrow * 36 + xq) * 4;
            const unsigned woff = bb + (unsigned)(XTILE_F + wrow * 36 + wq) * 4;
            cp16(xoff + sb,      xg + k0);
            cp16(xoff + sb + 64, xg + k0 + 16);
            cp16(woff + sb,      wg + k0);
            asm volatile("cp.async.commit_group;\n");
            asm volatile("cp.async.wait_group 1;\n");
        } else {
            asm volatile("cp.async.wait_group 0;\n");
        }
        __syncthreads();   // B1: buf c staged; previous compute done

        if (wid < 4) {
            // -------- convert fp32 tiles -> fp16 tiles (128 threads) --------
            const float* XF = smf[buf];
            const float* WF = smf[buf] + XTILE_F;
            __half2* X16 = (__half2*)x16s;   // [64][20]
            __half2* W16 = (__half2*)w16s;   // [32][20]
#pragma unroll
            for (int q = 0; q < 8; ++q) {    // X: 1024 half2 pairs
                const int p = q * 128 + tid;
                const int r = p >> 4, kp = p & 15;
                float2 v = *(const float2*)&XF[r * 36 + kp * 2];
                X16[r * 20 + kp] = __floats2half2_rn(v.x, v.y);
            }
#pragma unroll
            for (int q = 0; q < 4; ++q) {    // W: 512 half2 pairs
                const int p = q * 128 + tid;
                const int r = p >> 4, kp = p & 15;
                float2 v = *(const float2*)&WF[r * 36 + kp * 2];
                W16[r * 20 + kp] = __floats2half2_rn(v.x, v.y);
            }
            asm volatile("bar.sync 1, 128;" ::: "memory");

            // -------- MAX term: packed fp16 (HMUL2 + HMAX2) ----------------
#pragma unroll
            for (int kk = 0; kk < 32; kk += 8) {
                uint4 xv[4], wv[4];
#pragma unroll
                for (int i = 0; i < 4; i++)
                    xv[i] = *(const uint4*)&x16s[(trow * 4 + i) * 40 + kk];
#pragma unroll
                for (int j = 0; j < 4; j++)
                    wv[j] = *(const uint4*)&w16s[(tcol + 8 * j) * 40 + kk];
#pragma unroll
                for (int i = 0; i < 4; i++)
#pragma unroll
                    for (int j = 0; j < 4; j++) {
                        const __half2* xh = (const __half2*)&xv[i];
                        const __half2* wh = (const __half2*)&wv[j];
#pragma unroll
                        for (int e = 0; e < 4; e++)
                            mx[i][j] = __hmax2(mx[i][j], __hmul2(xh[e], wh[e]));
                    }
            }
        } else {
            // -------- GEMM warps: 2-pass (X hi/lo vs W hi) -----------------
            const float* XF = smf[buf];
            const float* WF = smf[buf] + XTILE_F;
#pragma unroll
            for (int kc = 0; kc < 32; kc += 8) {
                uint32_t ah[2][4], al[2][4];
#pragma unroll
                for (int mt = 0; mt < 2; mt++) {
                    const int base = (wm * 32 + mt * 16 + lr) * 36 + kc + lw;
                    float f0 = XF[base],     f1 = XF[base + 8 * 36];
                    float f2 = XF[base + 4], f3 = XF[base + 8 * 36 + 4];
                    float h0 = tf32_of(f0), h1 = tf32_of(f1);
                    float h2 = tf32_of(f2), h3 = tf32_of(f3);
                    ah[mt][0] = __float_as_uint(h0); al[mt][0] = __float_as_uint(f0 - h0);
                    ah[mt][1] = __float_as_uint(h1); al[mt][1] = __float_as_uint(f1 - h1);
                    ah[mt][2] = __float_as_uint(h2); al[mt][2] = __float_as_uint(f2 - h2);
                    ah[mt][3] = __float_as_uint(h3); al[mt][3] = __float_as_uint(f3 - h3);
                }
#pragma unroll
                for (int nt = 0; nt < 2; nt++) {
                    const int base = (wn * 16 + nt * 8 + lr) * 36 + kc + lw;
                    uint32_t bh[2];
                    bh[0] = __float_as_uint(tf32_of(WF[base]));
                    bh[1] = __float_as_uint(tf32_of(WF[base + 4]));
#pragma unroll
                    for (int mt = 0; mt < 2; mt++) {
                        mma_tf32(acc[mt][nt], ah[mt], bh);
                        mma_tf32(acc[mt][nt], al[mt], bh);
                    }
                }
            }
        }
        __syncthreads();   // B2: compute(c) done
    }

    // ---- epilogue: max warps publish mx, gemm warps combine + store -------
    float* mxs = smf[0];   // [64][36]; buffer 0 free (last chunk uses buf 1)
    if (wid < 4) {
#pragma unroll
        for (int i = 0; i < 4; i++)
#pragma unroll
            for (int j = 0; j < 4; j++) {
                float m = fmaxf(__low2float(mx[i][j]), __high2float(mx[i][j]));
                mxs[(trow * 4 + i) * 36 + tcol + 8 * j] = BETA * m;
            }
    }
    __syncthreads();

    if (wid >= 4) {
#pragma unroll
        for (int mt = 0; mt < 2; mt++) {
            const int r0 = wm * 32 + mt * 16 + lr;
#pragma unroll
            for (int nt = 0; nt < 2; nt++) {
                const int cc = wn * 16 + nt * 8 + lw * 2;
                const float2 bia = *(const float2*)&bias[n0 + cc];

                float a0 = 0.8f * acc[mt][nt][0] + bia.x + mxs[r0 * 36 + cc];
                float a1 = 0.8f * acc[mt][nt][1] + bia.y + mxs[r0 * 36 + cc + 1];
                float a2 = 0.8f * acc[mt][nt][2] + bia.x + mxs[(r0 + 8) * 36 + cc];
                float a3 = 0.8f * acc[mt][nt][3] + bia.y + mxs[(r0 + 8) * 36 + cc + 1];

                const size_t o0 = (size_t)(m0 + r0) * O + n0 + cc;
                const size_t o1 = (size_t)(m0 + r0 + 8) * O + n0 + cc;
                *(float2*)&act[o0] = make_float2(a0, a1);
                *(float2*)&act[o1] = make_float2(a2, a3);
            }
        }
    }
}

// ---------------- final layer ----------------------------------------------
__global__ void __launch_bounds__(256)
layer4_kernel(const float* __restrict__ X, const float* __restrict__ W,
              const float* __restrict__ bias, float* __restrict__ out, int B)
{
    const int row = blockIdx.x * 8 + (threadIdx.x >> 5);
    const int lane = threadIdx.x & 31;
    if (row >= B) return;

    const float4* xr = (const float4*)(X + (size_t)row * 512);
    const float4* wr = (const float4*)W;

    float acc = 0.0f;
    float mx = -CUDART_INF_F;
#pragma unroll
    for (int it = 0; it < 4; ++it) {
        float4 x = xr[lane + 32 * it];
        float4 w = wr[lane + 32 * it];
        float p0 = x.x * w.x, p1 = x.y * w.y, p2 = x.z * w.z, p3 = x.w * w.w;
        acc += (p0 + p1) + (p2 + p3);
        mx = fmaxf(fmaxf(mx, fmaxf(p0, p1)), fmaxf(p2, p3));
    }
#pragma unroll
    for (int o = 16; o > 0; o >>= 1) {
        acc += __shfl_xor_sync(0xffffffff, acc, o);
        mx = fmaxf(mx, __shfl_xor_sync(0xffffffff, mx, o));
    }
    if (lane == 0)
        out[row] = (1.0f - BETA) * acc + BETA * mx + bias[0];
}

// ---------------- launch ----------------------------------------------------
extern "C" void kernel_launch(void* const* d_in, const int* in_sizes, int n_in,
                              void* d_out, int out_size)
{
    const float* x  = (const float*)d_in[0];
    const float* W1 = (const float*)d_in[1];
    const float* b1 = (const float*)d_in[2];
    const float* W2 = (const float*)d_in[3];
    const float* b2 = (const float*)d_in[4];
    const float* W3 = (const float*)d_in[5];
    const float* b3 = (const float*)d_in[6];
    const float* W4 = (const float*)d_in[7];
    const float* b4 = (const float*)d_in[8];
    float* out = (float*)d_out;

    const int WID = in_sizes[2];        // 512
    const int IN  = in_sizes[1] / WID;  // 256
    const int B   = in_sizes[0] / IN;   // 1024

    float *actA, *actB;
    cudaGetSymbolAddress((void**)&actA, g_actA);
    cudaGetSymbolAddress((void**)&actB, g_actB);

    const dim3 blk(256);
    const dim3 grid(256);   // 16 m-tiles x 16 n-tiles of 64x32

    layer_fused<256><<<grid, blk>>>(x,    W1, b1, actA, WID);
    layer_fused<512><<<grid, blk>>>(actA, W2, b2, actB, WID);
    layer_fused<512><<<grid, blk>>>(actB, W3, b3, actA, WID);
    layer4_kernel<<<B / 8, blk>>>(actA, W4, b4, out, B);
}